// round 10
// baseline (speedup 1.0000x reference)
#include <cuda_runtime.h>

// Problem constants (shapes fixed by setup_inputs)
#define Bc   8
#define Nc   4096
#define Cc   64
#define COc  128
#define KNN  8
#define CAP  2048            /* candidate capacity per row (mean ~600, huge margin) */

#define ROWS_TOTAL   (Bc*Nc)           /* 32768 */
#define CONV_ROWS    16
#define CONV_BLOCKS  (ROWS_TOTAL/CONV_ROWS)  /* 2048 */

// ---------------- scratch (device globals: no runtime allocation) ----------
__device__ float g_xx[Bc*Nc];                       // per-point squared norms
__device__ int   g_cnt[Bc*Nc];                      // per-row candidate counts
__device__ uint2 g_cand[(size_t)Nc*CAP];            // 64MB candidate buffer (reused per batch)
__device__ float g_feat[(size_t)ROWS_TOTAL*Cc];     // 8MB  gathered-max features
__device__ float g_psum[CONV_BLOCKS*COc];           // BN partial sums (deterministic)
__device__ float g_psumsq[CONV_BLOCKS*COc];
__device__ float g_mean[COc];
__device__ float g_rstd[COc];

// ---------------- squared norms + counter zeroing ---------------------------
__global__ __launch_bounds__(256) void k_xx(const float* __restrict__ x)
{
    int gw   = (blockIdx.x*256 + threadIdx.x) >> 5;   // warp per row
    int lane = threadIdx.x & 31;
    if (gw >= ROWS_TOTAL) return;
    const float* xr = x + (size_t)gw*Cc;
    float a = xr[lane], b = xr[lane+32];
    float s = a*a + b*b;
    #pragma unroll
    for (int o=16;o;o>>=1) s += __shfl_xor_sync(0xffffffffu, s, o);
    if (lane == 0){ g_xx[gw] = s; g_cnt[gw] = 0; }
}

// ---------------- distance GEMM + smem-staged candidate filter --------------
// D[n][m] = 2*<x_n,x_m> - xx_n - xx_m. Main loop is the R3 58.7us SGEMM,
// untouched. Epilogue stages acc through smem (acc dies -> no register
// pressure bleed into the main loop), then warp-per-row threshold + ballot
// compaction appends survivors to per-row candidate lists.
__global__ __launch_bounds__(256, 2) void k_dist(const float* __restrict__ x, int b)
{
    __shared__ float As[32][128];   // k-major; reused as 64x128 stage in epilogue
    __shared__ float Bs[32][128];
    const float* xb = x + (size_t)b*Nc*Cc;
    const int n0  = blockIdx.y*128;
    const int m0  = blockIdx.x*128;
    const int tid = threadIdx.x;
    const int tx  = tid & 15;
    const int ty  = tid >> 4;
    const int lane = tid & 31;
    const int warp = tid >> 5;
    const int lrow = tid & 127;
    const int lk0  = (tid >> 7) * 4;

    float acc[8][8];
    #pragma unroll
    for (int i=0;i<8;i++)
        #pragma unroll
        for (int j=0;j<8;j++) acc[i][j] = 0.f;

    #pragma unroll
    for (int kk=0; kk<2; kk++){
        #pragma unroll
        for (int i=0;i<4;i++){
            int k4 = lk0 + i*8;
            float4 a = *reinterpret_cast<const float4*>(&xb[(size_t)(n0+lrow)*Cc + kk*32 + k4]);
            As[k4+0][lrow]=a.x; As[k4+1][lrow]=a.y; As[k4+2][lrow]=a.z; As[k4+3][lrow]=a.w;
            float4 bb = *reinterpret_cast<const float4*>(&xb[(size_t)(m0+lrow)*Cc + kk*32 + k4]);
            Bs[k4+0][lrow]=bb.x; Bs[k4+1][lrow]=bb.y; Bs[k4+2][lrow]=bb.z; Bs[k4+3][lrow]=bb.w;
        }
        __syncthreads();
        #pragma unroll
        for (int k=0;k<32;k++){
            float4 a0 = *reinterpret_cast<const float4*>(&As[k][ty*4]);
            float4 a1 = *reinterpret_cast<const float4*>(&As[k][64+ty*4]);
            float4 b0 = *reinterpret_cast<const float4*>(&Bs[k][tx*4]);
            float4 b1 = *reinterpret_cast<const float4*>(&Bs[k][64+tx*4]);
            float av[8]={a0.x,a0.y,a0.z,a0.w,a1.x,a1.y,a1.z,a1.w};
            float bv[8]={b0.x,b0.y,b0.z,b0.w,b1.x,b1.y,b1.z,b1.w};
            #pragma unroll
            for (int i=0;i<8;i++)
                #pragma unroll
                for (int j=0;j<8;j++)
                    acc[i][j] = fmaf(av[i], bv[j], acc[i][j]);
        }
        __syncthreads();
    }

    // ---- epilogue: two 64-row passes staged through the 32KB smem ----------
    float (*S)[128] = reinterpret_cast<float(*)[128]>(&As[0][0]);
    // this lane's 4 column norms (contiguous -> one LDG.128); same for all rows
    float4 cxx = *reinterpret_cast<const float4*>(&g_xx[b*Nc + m0 + lane*4]);

    #pragma unroll
    for (int rq=0; rq<2; rq++){
        __syncthreads();
        #pragma unroll
        for (int r=0;r<4;r++){
            int lr = ty*4 + r;
            #pragma unroll
            for (int cq=0;cq<2;cq++){
                float4 v = make_float4(acc[rq*4+r][cq*4+0], acc[rq*4+r][cq*4+1],
                                       acc[rq*4+r][cq*4+2], acc[rq*4+r][cq*4+3]);
                *reinterpret_cast<float4*>(&S[lr][cq*64 + tx*4]) = v;
            }
        }
        __syncthreads();

        // row norms for this warp's 8 rows: one coalesced load, shfl-distributed
        float xn8 = (lane < 8) ? g_xx[b*Nc + n0 + rq*64 + warp*8 + lane] : 0.f;

        // warp w owns local rows w*8 .. w*8+7 of this 64-row half
        #pragma unroll
        for (int rr=0; rr<8; rr++){
            int lr  = warp*8 + rr;
            int row = n0 + rq*64 + lr;
            float xn = __shfl_sync(0xffffffffu, xn8, rr);
            float4 p = *reinterpret_cast<const float4*>(&S[lr][lane*4]);
            float d0 = 2.f*p.x - xn - cxx.x;
            float d1 = 2.f*p.y - xn - cxx.y;
            float d2 = 2.f*p.z - xn - cxx.z;
            float d3 = 2.f*p.w - xn - cxx.w;

            // threshold: min of 8 distinct 16-element block maxes
            // (8 distinct elements >= t  =>  t <= true 8th best of this tile row)
            float m4 = fmaxf(fmaxf(d0,d1), fmaxf(d2,d3));
            m4 = fmaxf(m4, __shfl_xor_sync(0xffffffffu, m4, 1));
            m4 = fmaxf(m4, __shfl_xor_sync(0xffffffffu, m4, 2));   // 16-elem block max
            float t = fminf(m4, __shfl_xor_sync(0xffffffffu, m4, 4));
            t = fminf(t, __shfl_xor_sync(0xffffffffu, t, 8));
            t = fminf(t, __shfl_xor_sync(0xffffffffu, t, 16));

            uint2* brow = &g_cand[(size_t)row*CAP];
            int*   cp   = &g_cnt[b*Nc + row];
            float dd[4] = {d0,d1,d2,d3};
            #pragma unroll
            for (int c=0;c<4;c++){
                bool f = (dd[c] >= t);
                unsigned msk = __ballot_sync(0xffffffffu, f);
                if (msk){
                    int base;
                    if (lane == 0) base = atomicAdd(cp, __popc(msk));
                    base = __shfl_sync(0xffffffffu, base, 0);
                    if (f){
                        int off = base + __popc(msk & ((1u<<lane)-1u));
                        if (off < CAP)
                            brow[off] = make_uint2(__float_as_uint(dd[c]),
                                                   (unsigned)(m0 + lane*4 + c));
                    }
                }
            }
        }
    }
}

// ---------------- exact top-k(8) over candidates + gather + channel max -----
__device__ __forceinline__ bool knn_better(float v1,int i1,float v2,int i2){
    return (v1 > v2) || (v1 == v2 && i1 < i2);   // matches lax.top_k tie-break
}

__device__ __forceinline__ void knn_insert(float (&v)[8], int (&id)[8], float cv, int ci){
    if (!knn_better(cv,ci,v[7],id[7])) return;
    #pragma unroll
    for (int j=0;j<8;j++){
        if (knn_better(cv,ci,v[j],id[j])){
            float tv=v[j]; int ti=id[j];
            v[j]=cv; id[j]=ci;
            cv=tv; ci=ti;
        }
    }
}

__global__ __launch_bounds__(256) void k_select(const float* __restrict__ x, int b)
{
    int gw   = (blockIdx.x*256 + threadIdx.x) >> 5;   // warp per n-row
    int lane = threadIdx.x & 31;
    if (gw >= Nc) return;
    const int n = gw;
    int cnt = g_cnt[b*Nc + n];
    if (cnt > CAP) cnt = CAP;
    const uint2* brow = &g_cand[(size_t)n*CAP];

    float v[8]; int id[8];
    #pragma unroll
    for (int j=0;j<8;j++){ v[j] = __int_as_float(0xff800000u); id[j] = 0x7fffffff; }

    for (int ci = lane; ci < cnt; ci += 32){
        uint2 e = brow[ci];
        knn_insert(v, id, __uint_as_float(e.x), (int)e.y);
    }

    int knn_idx[8];
    #pragma unroll
    for (int r=0;r<KNN;r++){
        float bv = v[0]; int bi = id[0];
        #pragma unroll
        for (int o=16;o;o>>=1){
            float ov = __shfl_xor_sync(0xffffffffu, bv, o);
            int   oi = __shfl_xor_sync(0xffffffffu, bi, o);
            if (knn_better(ov,oi,bv,bi)){ bv=ov; bi=oi; }
        }
        knn_idx[r] = bi;                 // all lanes agree
        if (id[0] == bi){                // owning lane pops its head
            #pragma unroll
            for (int j=0;j<7;j++){ v[j]=v[j+1]; id[j]=id[j+1]; }
            v[7] = __int_as_float(0xff800000u); id[7] = 0x7fffffff;
        }
    }

    // gather neighbor features and take channel-wise max (exact, order-free)
    const float* xb = x + (size_t)b*Nc*Cc;
    #pragma unroll
    for (int cc=0; cc<2; cc++){
        int c = lane + cc*32;
        float m = xb[(size_t)knn_idx[0]*Cc + c];
        #pragma unroll
        for (int r=1;r<KNN;r++)
            m = fmaxf(m, xb[(size_t)knn_idx[r]*Cc + c]);
        g_feat[((size_t)b*Nc + n)*Cc + c] = m;
    }
}

// ---------------- 1x1 conv GEMM + deterministic BN partials -----------------
__global__ __launch_bounds__(128) void k_conv(const float* __restrict__ W,
                                              float* __restrict__ y)
{
    __shared__ float Ws[COc][Cc+1];   // +1 pad: conflict-free per-thread rows
    __shared__ float Fs[CONV_ROWS][Cc];
    const int t    = threadIdx.x;     // 128 threads == one output channel each
    const int blk  = blockIdx.x;
    const int row0 = blk*CONV_ROWS;

    for (int i=t; i<COc*Cc; i+=128) Ws[i>>6][i&63] = W[i];
    for (int i=t; i<CONV_ROWS*Cc; i+=128) Fs[i>>6][i&63] = g_feat[(size_t)row0*Cc + i];
    __syncthreads();

    const int o = t;
    float acc[CONV_ROWS];
    #pragma unroll
    for (int r=0;r<CONV_ROWS;r++) acc[r]=0.f;

    #pragma unroll 8
    for (int k=0;k<Cc;k++){
        float w = Ws[o][k];
        #pragma unroll
        for (int r=0;r<CONV_ROWS;r++)
            acc[r] = fmaf(Fs[r][k], w, acc[r]);
    }

    float s=0.f, s2=0.f;
    #pragma unroll
    for (int r=0;r<CONV_ROWS;r++){
        float yv = acc[r];
        y[(size_t)(row0+r)*COc + o] = yv;
        s  += yv;
        s2 += yv*yv;
    }
    g_psum  [blk*COc + o] = s;
    g_psumsq[blk*COc + o] = s2;
}

// ---------------- BN stats (fixed-order, deterministic) ---------------------
__global__ __launch_bounds__(COc) void k_stats()
{
    int o = threadIdx.x;
    float s=0.f, s2=0.f;
    for (int i=0;i<CONV_BLOCKS;i++){
        s  += g_psum  [i*COc + o];
        s2 += g_psumsq[i*COc + o];
    }
    const float invM = 1.f / (float)ROWS_TOTAL;
    float mean = s * invM;
    float var  = s2 * invM - mean*mean;
    g_mean[o] = mean;
    g_rstd[o] = rsqrtf(var + 1e-5f);
}

// ---------------- BN apply + LeakyReLU --------------------------------------
__device__ __forceinline__ float bn_lrelu(float val, int o,
                                          const float* __restrict__ gamma,
                                          const float* __restrict__ beta){
    float z = (val - g_mean[o]) * g_rstd[o] * gamma[o] + beta[o];
    return z >= 0.f ? z : 0.01f*z;
}

__global__ __launch_bounds__(256) void k_apply(const float* __restrict__ gamma,
                                               const float* __restrict__ beta,
                                               float* __restrict__ y)
{
    int i = blockIdx.x*256 + threadIdx.x;
    const int total4 = Bc*Nc*COc/4;
    if (i >= total4) return;
    int o = (i*4) & (COc-1);
    float4 t = reinterpret_cast<float4*>(y)[i];
    t.x = bn_lrelu(t.x, o+0, gamma, beta);
    t.y = bn_lrelu(t.y, o+1, gamma, beta);
    t.z = bn_lrelu(t.z, o+2, gamma, beta);
    t.w = bn_lrelu(t.w, o+3, gamma, beta);
    reinterpret_cast<float4*>(y)[i] = t;
}

// ---------------- launch ----------------------------------------------------
extern "C" void kernel_launch(void* const* d_in, const int* in_sizes, int n_in,
                              void* d_out, int out_size)
{
    const float* x     = (const float*)d_in[0];
    const float* W     = (const float*)d_in[1];
    const float* gamma = (const float*)d_in[2];
    const float* beta  = (const float*)d_in[3];
    float* y = (float*)d_out;

    k_xx<<<ROWS_TOTAL/8, 256>>>(x);   // norms + zero all candidate counters

    dim3 dg(Nc/128, Nc/128);   // 32 x 32 tiles
    for (int b=0; b<Bc; b++){
        k_dist<<<dg, 256>>>(x, b);        // fused GEMM + smem-staged filter
        k_select<<<Nc/8, 256>>>(x, b);    // exact top-8 over ~600 candidates/row
    }

    k_conv<<<CONV_BLOCKS, 128>>>(W, y);
    k_stats<<<1, COc>>>();
    k_apply<<<(Bc*Nc*COc/4 + 255)/256, 256>>>(gamma, beta, y);
}

// round 11
// speedup vs baseline: 2.1581x; 2.1581x over previous
#include <cuda_runtime.h>

// Problem constants (shapes fixed by setup_inputs)
#define Bc   8
#define Nc   4096
#define Cc   64
#define COc  128
#define KNN  8
#define NTILE 32             /* 4096 / 128 column tiles */

#define ROWS_TOTAL   (Bc*Nc)           /* 32768 */
#define CONV_ROWS    16
#define CONV_BLOCKS  (ROWS_TOTAL/CONV_ROWS)  /* 2048 */

// ---------------- scratch (device globals: no runtime allocation) ----------
__device__ float g_xx[Bc*Nc];                       // per-point squared norms
__device__ float g_dist[(size_t)Nc*Nc];             // 64MB, reused per batch (L2-resident)
__device__ float g_tmax[(size_t)Nc*NTILE];          // per (row, 128-col tile) max
__device__ float g_feat[(size_t)ROWS_TOTAL*Cc];     // 8MB  gathered-max features
__device__ float g_psum[CONV_BLOCKS*COc];           // BN partial sums (deterministic)
__device__ float g_psumsq[CONV_BLOCKS*COc];
__device__ float g_mean[COc];
__device__ float g_rstd[COc];

// ---------------- squared norms --------------------------------------------
__global__ __launch_bounds__(256) void k_xx(const float* __restrict__ x)
{
    int gw   = (blockIdx.x*256 + threadIdx.x) >> 5;   // warp per row
    int lane = threadIdx.x & 31;
    if (gw >= ROWS_TOTAL) return;
    const float* xr = x + (size_t)gw*Cc;
    float a = xr[lane], b = xr[lane+32];
    float s = a*a + b*b;
    #pragma unroll
    for (int o=16;o;o>>=1) s += __shfl_xor_sync(0xffffffffu, s, o);
    if (lane == 0) g_xx[gw] = s;
}

// ---------------- distance GEMM (R3 58.7us mainloop) + per-tile row maxes ---
// D[n][m] = 2*<x_n,x_m> - xx_n - xx_m, written in full to g_dist (L2-resident).
// Only addition vs R3: each (row, 128-col tile) max -> g_tmax. ~15 extra ops
// per row, one extra register, no atomics, no flags.
__global__ __launch_bounds__(256, 2) void k_dist(const float* __restrict__ x, int b)
{
    __shared__ float As[32][128];   // k-major
    __shared__ float Bs[32][128];
    const float* xb = x + (size_t)b*Nc*Cc;
    const int n0  = blockIdx.y*128;
    const int m0  = blockIdx.x*128;
    const int tid = threadIdx.x;
    const int tx  = tid & 15;
    const int ty  = tid >> 4;
    const int lrow = tid & 127;
    const int lk0  = (tid >> 7) * 4;

    float acc[8][8];
    #pragma unroll
    for (int i=0;i<8;i++)
        #pragma unroll
        for (int j=0;j<8;j++) acc[i][j] = 0.f;

    #pragma unroll
    for (int kk=0; kk<2; kk++){
        #pragma unroll
        for (int i=0;i<4;i++){
            int k4 = lk0 + i*8;
            float4 a = *reinterpret_cast<const float4*>(&xb[(size_t)(n0+lrow)*Cc + kk*32 + k4]);
            As[k4+0][lrow]=a.x; As[k4+1][lrow]=a.y; As[k4+2][lrow]=a.z; As[k4+3][lrow]=a.w;
            float4 bb = *reinterpret_cast<const float4*>(&xb[(size_t)(m0+lrow)*Cc + kk*32 + k4]);
            Bs[k4+0][lrow]=bb.x; Bs[k4+1][lrow]=bb.y; Bs[k4+2][lrow]=bb.z; Bs[k4+3][lrow]=bb.w;
        }
        __syncthreads();
        #pragma unroll
        for (int k=0;k<32;k++){
            float4 a0 = *reinterpret_cast<const float4*>(&As[k][ty*4]);
            float4 a1 = *reinterpret_cast<const float4*>(&As[k][64+ty*4]);
            float4 b0 = *reinterpret_cast<const float4*>(&Bs[k][tx*4]);
            float4 b1 = *reinterpret_cast<const float4*>(&Bs[k][64+tx*4]);
            float av[8]={a0.x,a0.y,a0.z,a0.w,a1.x,a1.y,a1.z,a1.w};
            float bv[8]={b0.x,b0.y,b0.z,b0.w,b1.x,b1.y,b1.z,b1.w};
            #pragma unroll
            for (int i=0;i<8;i++)
                #pragma unroll
                for (int j=0;j<8;j++)
                    acc[i][j] = fmaf(av[i], bv[j], acc[i][j]);
        }
        __syncthreads();
    }

    float mxx[8];
    #pragma unroll
    for (int cq=0;cq<2;cq++)
        #pragma unroll
        for (int c=0;c<4;c++)
            mxx[cq*4+c] = g_xx[b*Nc + m0 + cq*64 + tx*4 + c];

    // Epilogue: the 16 threads sharing ty (a half-warp: tids ty*16..ty*16+15)
    // own the same 8 rows and together cover the 128 columns of this tile.
    #pragma unroll
    for (int rq=0;rq<2;rq++){
        #pragma unroll
        for (int r=0;r<4;r++){
            int row = n0 + rq*64 + ty*4 + r;
            float xn = g_xx[b*Nc + row];
            int ai = rq*4 + r;
            float d[8];
            #pragma unroll
            for (int j=0;j<8;j++) d[j] = 2.f*acc[ai][j] - xn - mxx[j];

            *reinterpret_cast<float4*>(&g_dist[(size_t)row*Nc + m0 + tx*4]) =
                make_float4(d[0], d[1], d[2], d[3]);
            *reinterpret_cast<float4*>(&g_dist[(size_t)row*Nc + m0 + 64 + tx*4]) =
                make_float4(d[4], d[5], d[6], d[7]);

            // tile max for this row (reduce over the 16-lane half-warp group)
            float m = d[0];
            #pragma unroll
            for (int j=1;j<8;j++) m = fmaxf(m, d[j]);
            m = fmaxf(m, __shfl_xor_sync(0xffffffffu, m, 1));
            m = fmaxf(m, __shfl_xor_sync(0xffffffffu, m, 2));
            m = fmaxf(m, __shfl_xor_sync(0xffffffffu, m, 4));
            m = fmaxf(m, __shfl_xor_sync(0xffffffffu, m, 8));
            if (tx == 0) g_tmax[(size_t)row*NTILE + blockIdx.x] = m;
        }
    }
}

// ---------------- tile-pruned exact top-k(8) + gather + channel max ---------
__device__ __forceinline__ bool knn_better(float v1,int i1,float v2,int i2){
    return (v1 > v2) || (v1 == v2 && i1 < i2);   // matches lax.top_k tie-break
}

__device__ __forceinline__ void knn_insert(float (&v)[8], int (&id)[8], float cv, int ci){
    if (!knn_better(cv,ci,v[7],id[7])) return;
    #pragma unroll
    for (int j=0;j<8;j++){
        if (knn_better(cv,ci,v[j],id[j])){
            float tv=v[j]; int ti=id[j];
            v[j]=cv; id[j]=ci;
            cv=tv; ci=ti;
        }
    }
}

__global__ __launch_bounds__(256) void k_topk(const float* __restrict__ x, int b)
{
    int gw   = (blockIdx.x*256 + threadIdx.x) >> 5;   // warp per n-row
    int lane = threadIdx.x & 31;
    if (gw >= Nc) return;
    const int n = gw;
    const float NEG_INF = __int_as_float(0xff800000);

    // t8 = 8th-largest of the 32 tile maxes. The top-8 tile maxes are 8
    // distinct row elements >= t8, so t8 <= true 8th-best of the row; any
    // tile with max < t8 contains no global-top-8 element.
    float tm  = g_tmax[(size_t)n*NTILE + lane];
    float cur = tm, t8 = tm;
    #pragma unroll
    for (int r=0;r<KNN;r++){
        float m = cur;
        #pragma unroll
        for (int o=16;o;o>>=1) m = fmaxf(m, __shfl_xor_sync(0xffffffffu, m, o));
        t8 = m;
        unsigned msk = __ballot_sync(0xffffffffu, cur == m);
        if (lane == (__ffs(msk) - 1)) cur = NEG_INF;   // drop one instance
    }

    float v[8]; int id[8];
    #pragma unroll
    for (int j=0;j<8;j++){ v[j] = NEG_INF; id[j] = 0x7fffffff; }

    const float* drow = &g_dist[(size_t)n*Nc];
    unsigned keep = __ballot_sync(0xffffffffu, tm >= t8);   // ~8 tiles survive
    while (keep){
        int tile = __ffs(keep) - 1;
        keep &= keep - 1;
        int ci = tile*128 + lane*4;
        float4 d = *reinterpret_cast<const float4*>(&drow[ci]);
        if (d.x >= t8) knn_insert(v,id,d.x,ci+0);
        if (d.y >= t8) knn_insert(v,id,d.y,ci+1);
        if (d.z >= t8) knn_insert(v,id,d.z,ci+2);
        if (d.w >= t8) knn_insert(v,id,d.w,ci+3);
    }

    int knn_idx[8];
    #pragma unroll
    for (int r=0;r<KNN;r++){
        float bv = v[0]; int bi = id[0];
        #pragma unroll
        for (int o=16;o;o>>=1){
            float ov = __shfl_xor_sync(0xffffffffu, bv, o);
            int   oi = __shfl_xor_sync(0xffffffffu, bi, o);
            if (knn_better(ov,oi,bv,bi)){ bv=ov; bi=oi; }
        }
        knn_idx[r] = bi;                 // all lanes agree
        if (id[0] == bi){                // owning lane pops its head
            #pragma unroll
            for (int j=0;j<7;j++){ v[j]=v[j+1]; id[j]=id[j+1]; }
            v[7] = NEG_INF; id[7] = 0x7fffffff;
        }
    }

    // gather neighbor features and take channel-wise max (exact, order-free)
    const float* xb = x + (size_t)b*Nc*Cc;
    #pragma unroll
    for (int cc=0; cc<2; cc++){
        int c = lane + cc*32;
        float m = xb[(size_t)knn_idx[0]*Cc + c];
        #pragma unroll
        for (int r=1;r<KNN;r++)
            m = fmaxf(m, xb[(size_t)knn_idx[r]*Cc + c]);
        g_feat[((size_t)b*Nc + n)*Cc + c] = m;
    }
}

// ---------------- 1x1 conv GEMM + deterministic BN partials -----------------
__global__ __launch_bounds__(128) void k_conv(const float* __restrict__ W,
                                              float* __restrict__ y)
{
    __shared__ float Ws[COc][Cc+1];   // +1 pad: conflict-free per-thread rows
    __shared__ float Fs[CONV_ROWS][Cc];
    const int t    = threadIdx.x;     // 128 threads == one output channel each
    const int blk  = blockIdx.x;
    const int row0 = blk*CONV_ROWS;

    for (int i=t; i<COc*Cc; i+=128) Ws[i>>6][i&63] = W[i];
    for (int i=t; i<CONV_ROWS*Cc; i+=128) Fs[i>>6][i&63] = g_feat[(size_t)row0*Cc + i];
    __syncthreads();

    const int o = t;
    float acc[CONV_ROWS];
    #pragma unroll
    for (int r=0;r<CONV_ROWS;r++) acc[r]=0.f;

    #pragma unroll 8
    for (int k=0;k<Cc;k++){
        float w = Ws[o][k];
        #pragma unroll
        for (int r=0;r<CONV_ROWS;r++)
            acc[r] = fmaf(Fs[r][k], w, acc[r]);
    }

    float s=0.f, s2=0.f;
    #pragma unroll
    for (int r=0;r<CONV_ROWS;r++){
        float yv = acc[r];
        y[(size_t)(row0+r)*COc + o] = yv;
        s  += yv;
        s2 += yv*yv;
    }
    g_psum  [blk*COc + o] = s;
    g_psumsq[blk*COc + o] = s2;
}

// ---------------- BN stats (fixed-order, deterministic) ---------------------
__global__ __launch_bounds__(COc) void k_stats()
{
    int o = threadIdx.x;
    float s=0.f, s2=0.f;
    for (int i=0;i<CONV_BLOCKS;i++){
        s  += g_psum  [i*COc + o];
        s2 += g_psumsq[i*COc + o];
    }
    const float invM = 1.f / (float)ROWS_TOTAL;
    float mean = s * invM;
    float var  = s2 * invM - mean*mean;
    g_mean[o] = mean;
    g_rstd[o] = rsqrtf(var + 1e-5f);
}

// ---------------- BN apply + LeakyReLU --------------------------------------
__device__ __forceinline__ float bn_lrelu(float val, int o,
                                          const float* __restrict__ gamma,
                                          const float* __restrict__ beta){
    float z = (val - g_mean[o]) * g_rstd[o] * gamma[o] + beta[o];
    return z >= 0.f ? z : 0.01f*z;
}

__global__ __launch_bounds__(256) void k_apply(const float* __restrict__ gamma,
                                               const float* __restrict__ beta,
                                               float* __restrict__ y)
{
    int i = blockIdx.x*256 + threadIdx.x;
    const int total4 = Bc*Nc*COc/4;
    if (i >= total4) return;
    int o = (i*4) & (COc-1);
    float4 t = reinterpret_cast<float4*>(y)[i];
    t.x = bn_lrelu(t.x, o+0, gamma, beta);
    t.y = bn_lrelu(t.y, o+1, gamma, beta);
    t.z = bn_lrelu(t.z, o+2, gamma, beta);
    t.w = bn_lrelu(t.w, o+3, gamma, beta);
    reinterpret_cast<float4*>(y)[i] = t;
}

// ---------------- launch ----------------------------------------------------
extern "C" void kernel_launch(void* const* d_in, const int* in_sizes, int n_in,
                              void* d_out, int out_size)
{
    const float* x     = (const float*)d_in[0];
    const float* W     = (const float*)d_in[1];
    const float* gamma = (const float*)d_in[2];
    const float* beta  = (const float*)d_in[3];
    float* y = (float*)d_out;

    k_xx<<<ROWS_TOTAL/8, 256>>>(x);

    dim3 dg(Nc/128, Nc/128);   // 32 x 32 tiles
    for (int b=0; b<Bc; b++){
        k_dist<<<dg, 256>>>(x, b);        // R3 GEMM + tile maxes
        k_topk<<<Nc/8, 256>>>(x, b);      // tile-pruned exact top-8 (~1/4 scan)
    }

    k_conv<<<CONV_BLOCKS, 128>>>(W, y);
    k_stats<<<1, COc>>>();
    k_apply<<<(Bc*Nc*COc/4 + 255)/256, 256>>>(gamma, beta, y);
}

// round 13
// speedup vs baseline: 2.3441x; 1.0862x over previous
#include <cuda_runtime.h>

// Problem constants (shapes fixed by setup_inputs)
#define Bc   8
#define Nc   4096
#define Cc   64
#define COc  128
#define KNN  8
#define NTILE 32             /* 4096 / 128 column tiles */

#define ROWS_TOTAL   (Bc*Nc)           /* 32768 */
#define CONV_ROWS    16
#define CONV_BLOCKS  (ROWS_TOTAL/CONV_ROWS)  /* 2048 */

// ---------------- scratch (device globals: no runtime allocation) ----------
__device__ float g_xx[Bc*Nc];                       // per-point squared norms
__device__ float g_dist[(size_t)Nc*Nc];             // 64MB, reused per batch (L2-resident)
__device__ float g_tmax[(size_t)Nc*NTILE];          // per (row, 128-col tile) max
__device__ float g_feat[(size_t)ROWS_TOTAL*Cc];     // 8MB  gathered-max features
__device__ float g_psum[CONV_BLOCKS*COc];           // BN partial sums (deterministic)
__device__ float g_psumsq[CONV_BLOCKS*COc];
__device__ float g_mean[COc];
__device__ float g_rstd[COc];

// packed f32x2 helpers (sm_103a: FFMA2 is reachable only via PTX fma.rn.f32x2)
__device__ __forceinline__ unsigned long long f32x2_dup(float v){
    unsigned long long r;
    asm("mov.b64 %0, {%1, %1};" : "=l"(r) : "f"(v));
    return r;
}
__device__ __forceinline__ void f32x2_fma(unsigned long long& d,
                                          unsigned long long a,
                                          unsigned long long b){
    asm("fma.rn.f32x2 %0, %1, %2, %0;" : "+l"(d) : "l"(a), "l"(b));
}
__device__ __forceinline__ float f32x2_half(unsigned long long p, int hi){
    float lo, h;
    asm("mov.b64 {%0, %1}, %2;" : "=f"(lo), "=f"(h) : "l"(p));
    return hi ? h : lo;
}

// ---------------- squared norms --------------------------------------------
__global__ __launch_bounds__(256) void k_xx(const float* __restrict__ x)
{
    int gw   = (blockIdx.x*256 + threadIdx.x) >> 5;   // warp per row
    int lane = threadIdx.x & 31;
    if (gw >= ROWS_TOTAL) return;
    const float* xr = x + (size_t)gw*Cc;
    float a = xr[lane], b = xr[lane+32];
    float s = a*a + b*b;
    #pragma unroll
    for (int o=16;o;o>>=1) s += __shfl_xor_sync(0xffffffffu, s, o);
    if (lane == 0) g_xx[gw] = s;
}

// ---------------- distance GEMM (packed FFMA2 mainloop) + per-tile maxes ----
// D[n][m] = 2*<x_n,x_m> - xx_n - xx_m, written in full to g_dist (L2-resident).
// Accumulators are packed fp32 pairs along i: accp[ii][j] = (acc[2ii][j],
// acc[2ii+1][j]). A-operand pairs come free from the LDS.128 quad; B values
// are dup-packed once per k (alu pipe). 32 FFMA2/k replaces 64 FFMA/k,
// bit-identical results.
__global__ __launch_bounds__(256, 2) void k_dist(const float* __restrict__ x, int b)
{
    __shared__ float As[32][128];   // k-major
    __shared__ float Bs[32][128];
    const float* xb = x + (size_t)b*Nc*Cc;
    const int n0  = blockIdx.y*128;
    const int m0  = blockIdx.x*128;
    const int tid = threadIdx.x;
    const int tx  = tid & 15;
    const int ty  = tid >> 4;
    const int lrow = tid & 127;
    const int lk0  = (tid >> 7) * 4;

    unsigned long long accp[4][8];   // (acc[2ii][j], acc[2ii+1][j])
    #pragma unroll
    for (int ii=0;ii<4;ii++)
        #pragma unroll
        for (int j=0;j<8;j++) accp[ii][j] = 0ull;

    #pragma unroll
    for (int kk=0; kk<2; kk++){
        #pragma unroll
        for (int i=0;i<4;i++){
            int k4 = lk0 + i*8;
            float4 a = *reinterpret_cast<const float4*>(&xb[(size_t)(n0+lrow)*Cc + kk*32 + k4]);
            As[k4+0][lrow]=a.x; As[k4+1][lrow]=a.y; As[k4+2][lrow]=a.z; As[k4+3][lrow]=a.w;
            float4 bb = *reinterpret_cast<const float4*>(&xb[(size_t)(m0+lrow)*Cc + kk*32 + k4]);
            Bs[k4+0][lrow]=bb.x; Bs[k4+1][lrow]=bb.y; Bs[k4+2][lrow]=bb.z; Bs[k4+3][lrow]=bb.w;
        }
        __syncthreads();
        #pragma unroll
        for (int k=0;k<32;k++){
            // A pairs: LDS.128 quads give aligned reg pairs -> free 64-bit views
            ulonglong2 ap01 = *reinterpret_cast<const ulonglong2*>(&As[k][ty*4]);
            ulonglong2 ap23 = *reinterpret_cast<const ulonglong2*>(&As[k][64+ty*4]);
            unsigned long long ap[4] = {ap01.x, ap01.y, ap23.x, ap23.y};
            float4 b0 = *reinterpret_cast<const float4*>(&Bs[k][tx*4]);
            float4 b1 = *reinterpret_cast<const float4*>(&Bs[k][64+tx*4]);
            float bv[8]={b0.x,b0.y,b0.z,b0.w,b1.x,b1.y,b1.z,b1.w};
            unsigned long long bb[8];
            #pragma unroll
            for (int j=0;j<8;j++) bb[j] = f32x2_dup(bv[j]);
            #pragma unroll
            for (int ii=0;ii<4;ii++)
                #pragma unroll
                for (int j=0;j<8;j++)
                    f32x2_fma(accp[ii][j], ap[ii], bb[j]);
        }
        __syncthreads();
    }

    float mxx[8];
    #pragma unroll
    for (int cq=0;cq<2;cq++)
        #pragma unroll
        for (int c=0;c<4;c++)
            mxx[cq*4+c] = g_xx[b*Nc + m0 + cq*64 + tx*4 + c];

    // Epilogue: the 16 threads sharing ty (a half-warp) own the same 8 rows
    // and together cover the 128 columns of this tile.
    // acc rows: ai=0..3 -> rows ty*4+ai (pair (2ii,2ii+1)),
    //           ai=4..7 -> rows 64+ty*4+(ai-4).
    #pragma unroll
    for (int rq=0;rq<2;rq++){
        #pragma unroll
        for (int r=0;r<4;r++){
            int row = n0 + rq*64 + ty*4 + r;
            float xn = g_xx[b*Nc + row];
            int ai = rq*4 + r;
            int ii = ai >> 1, hi = ai & 1;
            float d[8];
            #pragma unroll
            for (int j=0;j<8;j++)
                d[j] = 2.f*f32x2_half(accp[ii][j], hi) - xn - mxx[j];

            *reinterpret_cast<float4*>(&g_dist[(size_t)row*Nc + m0 + tx*4]) =
                make_float4(d[0], d[1], d[2], d[3]);
            *reinterpret_cast<float4*>(&g_dist[(size_t)row*Nc + m0 + 64 + tx*4]) =
                make_float4(d[4], d[5], d[6], d[7]);

            // tile max for this row (reduce over the 16-lane half-warp group)
            float m = d[0];
            #pragma unroll
            for (int j=1;j<8;j++) m = fmaxf(m, d[j]);
            m = fmaxf(m, __shfl_xor_sync(0xffffffffu, m, 1));
            m = fmaxf(m, __shfl_xor_sync(0xffffffffu, m, 2));
            m = fmaxf(m, __shfl_xor_sync(0xffffffffu, m, 4));
            m = fmaxf(m, __shfl_xor_sync(0xffffffffu, m, 8));
            if (tx == 0) g_tmax[(size_t)row*NTILE + blockIdx.x] = m;
        }
    }
}

// ---------------- tile-pruned exact top-k(8) + gather + channel max ---------
__device__ __forceinline__ bool knn_better(float v1,int i1,float v2,int i2){
    return (v1 > v2) || (v1 == v2 && i1 < i2);   // matches lax.top_k tie-break
}

__device__ __forceinline__ void knn_insert(float (&v)[8], int (&id)[8], float cv, int ci){
    if (!knn_better(cv,ci,v[7],id[7])) return;
    #pragma unroll
    for (int j=0;j<8;j++){
        if (knn_better(cv,ci,v[j],id[j])){
            float tv=v[j]; int ti=id[j];
            v[j]=cv; id[j]=ci;
            cv=tv; ci=ti;
        }
    }
}

__global__ __launch_bounds__(256) void k_topk(const float* __restrict__ x, int b)
{
    int gw   = (blockIdx.x*256 + threadIdx.x) >> 5;   // warp per n-row
    int lane = threadIdx.x & 31;
    if (gw >= Nc) return;
    const int n = gw;
    const float NEG_INF = __int_as_float(0xff800000);

    // t8 = 8th-largest of the 32 tile maxes. The top-8 tile maxes are 8
    // distinct row elements >= t8, so t8 <= true 8th-best of the row; any
    // tile with max < t8 contains no global-top-8 element.
    float tm  = g_tmax[(size_t)n*NTILE + lane];
    float cur = tm, t8 = tm;
    #pragma unroll
    for (int r=0;r<KNN;r++){
        float m = cur;
        #pragma unroll
        for (int o=16;o;o>>=1) m = fmaxf(m, __shfl_xor_sync(0xffffffffu, m, o));
        t8 = m;
        unsigned msk = __ballot_sync(0xffffffffu, cur == m);
        if (lane == (__ffs(msk) - 1)) cur = NEG_INF;   // drop one instance
    }

    float v[8]; int id[8];
    #pragma unroll
    for (int j=0;j<8;j++){ v[j] = NEG_INF; id[j] = 0x7fffffff; }

    const float* drow = &g_dist[(size_t)n*Nc];
    unsigned keep = __ballot_sync(0xffffffffu, tm >= t8);   // ~8 tiles survive
    while (keep){
        int tile = __ffs(keep) - 1;
        keep &= keep - 1;
        int ci = tile*128 + lane*4;
        float4 d = *reinterpret_cast<const float4*>(&drow[ci]);
        if (d.x >= t8) knn_insert(v,id,d.x,ci+0);
        if (d.y >= t8) knn_insert(v,id,d.y,ci+1);
        if (d.z >= t8) knn_insert(v,id,d.z,ci+2);
        if (d.w >= t8) knn_insert(v,id,d.w,ci+3);
    }

    int knn_idx[8];
    #pragma unroll
    for (int r=0;r<KNN;r++){
        float bv = v[0]; int bi = id[0];
        #pragma unroll
        for (int o=16;o;o>>=1){
            float ov = __shfl_xor_sync(0xffffffffu, bv, o);
            int   oi = __shfl_xor_sync(0xffffffffu, bi, o);
            if (knn_better(ov,oi,bv,bi)){ bv=ov; bi=oi; }
        }
        knn_idx[r] = bi;                 // all lanes agree
        if (id[0] == bi){                // owning lane pops its head
            #pragma unroll
            for (int j=0;j<7;j++){ v[j]=v[j+1]; id[j]=id[j+1]; }
            v[7] = NEG_INF; id[7] = 0x7fffffff;
        }
    }

    // gather neighbor features and take channel-wise max (exact, order-free)
    const float* xb = x + (size_t)b*Nc*Cc;
    #pragma unroll
    for (int cc=0; cc<2; cc++){
        int c = lane + cc*32;
        float m = xb[(size_t)knn_idx[0]*Cc + c];
        #pragma unroll
        for (int r=1;r<KNN;r++)
            m = fmaxf(m, xb[(size_t)knn_idx[r]*Cc + c]);
        g_feat[((size_t)b*Nc + n)*Cc + c] = m;
    }
}

// ---------------- 1x1 conv GEMM + deterministic BN partials -----------------
__global__ __launch_bounds__(128) void k_conv(const float* __restrict__ W,
                                              float* __restrict__ y)
{
    __shared__ float Ws[COc][Cc+1];   // +1 pad: conflict-free per-thread rows
    __shared__ float Fs[CONV_ROWS][Cc];
    const int t    = threadIdx.x;     // 128 threads == one output channel each
    const int blk  = blockIdx.x;
    const int row0 = blk*CONV_ROWS;

    for (int i=t; i<COc*Cc; i+=128) Ws[i>>6][i&63] = W[i];
    for (int i=t; i<CONV_ROWS*Cc; i+=128) Fs[i>>6][i&63] = g_feat[(size_t)row0*Cc + i];
    __syncthreads();

    const int o = t;
    float acc[CONV_ROWS];
    #pragma unroll
    for (int r=0;r<CONV_ROWS;r++) acc[r]=0.f;

    #pragma unroll 8
    for (int k=0;k<Cc;k++){
        float w = Ws[o][k];
        #pragma unroll
        for (int r=0;r<CONV_ROWS;r++)
            acc[r] = fmaf(Fs[r][k], w, acc[r]);
    }

    float s=0.f, s2=0.f;
    #pragma unroll
    for (int r=0;r<CONV_ROWS;r++){
        float yv = acc[r];
        y[(size_t)(row0+r)*COc + o] = yv;
        s  += yv;
        s2 += yv*yv;
    }
    g_psum  [blk*COc + o] = s;
    g_psumsq[blk*COc + o] = s2;
}

// ---------------- BN stats (fixed-order, deterministic) ---------------------
__global__ __launch_bounds__(COc) void k_stats()
{
    int o = threadIdx.x;
    float s=0.f, s2=0.f;
    for (int i=0;i<CONV_BLOCKS;i++){
        s  += g_psum  [i*COc + o];
        s2 += g_psumsq[i*COc + o];
    }
    const float invM = 1.f / (float)ROWS_TOTAL;
    float mean = s * invM;
    float var  = s2 * invM - mean*mean;
    g_mean[o] = mean;
    g_rstd[o] = rsqrtf(var + 1e-5f);
}

// ---------------- BN apply + LeakyReLU --------------------------------------
__device__ __forceinline__ float bn_lrelu(float val, int o,
                                          const float* __restrict__ gamma,
                                          const float* __restrict__ beta){
    float z = (val - g_mean[o]) * g_rstd[o] * gamma[o] + beta[o];
    return z >= 0.f ? z : 0.01f*z;
}

__global__ __launch_bounds__(256) void k_apply(const float* __restrict__ gamma,
                                               const float* __restrict__ beta,
                                               float* __restrict__ y)
{
    int i = blockIdx.x*256 + threadIdx.x;
    const int total4 = Bc*Nc*COc/4;
    if (i >= total4) return;
    int o = (i*4) & (COc-1);
    float4 t = reinterpret_cast<float4*>(y)[i];
    t.x = bn_lrelu(t.x, o+0, gamma, beta);
    t.y = bn_lrelu(t.y, o+1, gamma, beta);
    t.z = bn_lrelu(t.z, o+2, gamma, beta);
    t.w = bn_lrelu(t.w, o+3, gamma, beta);
    reinterpret_cast<float4*>(y)[i] = t;
}

// ---------------- launch ----------------------------------------------------
extern "C" void kernel_launch(void* const* d_in, const int* in_sizes, int n_in,
                              void* d_out, int out_size)
{
    const float* x     = (const float*)d_in[0];
    const float* W     = (const float*)d_in[1];
    const float* gamma = (const float*)d_in[2];
    const float* beta  = (const float*)d_in[3];
    float* y = (float*)d_out;

    k_xx<<<ROWS_TOTAL/8, 256>>>(x);

    dim3 dg(Nc/128, Nc/128);   // 32 x 32 tiles
    for (int b=0; b<Bc; b++){
        k_dist<<<dg, 256>>>(x, b);        // FFMA2 GEMM + tile maxes
        k_topk<<<Nc/8, 256>>>(x, b);      // tile-pruned exact top-8
    }

    k_conv<<<CONV_BLOCKS, 128>>>(W, y);
    k_stats<<<1, COc>>>();
    k_apply<<<(Bc*Nc*COc/4 + 255)/256, 256>>>(gamma, beta, y);
}

// round 17
// speedup vs baseline: 2.6805x; 1.1435x over previous
#include <cuda_runtime.h>

// Problem constants (shapes fixed by setup_inputs)
#define Bc   8
#define Nc   4096
#define Cc   64
#define COc  128
#define KNN  8
#define NTILE 32             /* 4096 / 128 column tiles */
#define NTRI  (NTILE*(NTILE+1)/2)   /* 528 upper-triangle tiles */

#define ROWS_TOTAL   (Bc*Nc)           /* 32768 */
#define CONV_ROWS    16
#define CONV_BLOCKS  (ROWS_TOTAL/CONV_ROWS)  /* 2048 */

// ---------------- scratch (device globals: no runtime allocation) ----------
__device__ float g_xx[Bc*Nc];                       // per-point squared norms
__device__ float g_dist[(size_t)Nc*Nc];             // 64MB, reused per batch (L2-resident)
__device__ float g_tmax[(size_t)Nc*NTILE];          // per (row, 128-col tile) max
__device__ float g_feat[(size_t)ROWS_TOTAL*Cc];     // 8MB  gathered-max features
__device__ float g_psum[CONV_BLOCKS*COc];           // BN partial sums (deterministic)
__device__ float g_psumsq[CONV_BLOCKS*COc];
__device__ float g_mean[COc];
__device__ float g_rstd[COc];

// packed f32x2 helpers (sm_103a: FFMA2 is reachable only via PTX fma.rn.f32x2)
__device__ __forceinline__ unsigned long long f32x2_dup(float v){
    unsigned long long r;
    asm("mov.b64 %0, {%1, %1};" : "=l"(r) : "f"(v));
    return r;
}
__device__ __forceinline__ void f32x2_fma(unsigned long long& d,
                                          unsigned long long a,
                                          unsigned long long b){
    asm("fma.rn.f32x2 %0, %1, %2, %0;" : "+l"(d) : "l"(a), "l"(b));
}
__device__ __forceinline__ void f32x2_unpack(unsigned long long p, float& lo, float& hi){
    asm("mov.b64 {%0, %1}, %2;" : "=f"(lo), "=f"(hi) : "l"(p));
}

// ---------------- squared norms --------------------------------------------
__global__ __launch_bounds__(256) void k_xx(const float* __restrict__ x)
{
    int gw   = (blockIdx.x*256 + threadIdx.x) >> 5;   // warp per row
    int lane = threadIdx.x & 31;
    if (gw >= ROWS_TOTAL) return;
    const float* xr = x + (size_t)gw*Cc;
    float a = xr[lane], b = xr[lane+32];
    float s = a*a + b*b;
    #pragma unroll
    for (int o=16;o;o>>=1) s += __shfl_xor_sync(0xffffffffu, s, o);
    if (lane == 0) g_xx[gw] = s;
}

// ---------------- symmetric distance GEMM (upper triangle only) -------------
// D[n][m] = 2*<x_n,x_m> - xx_n - xx_m = D[m][n]. Only tiles bi<=bj are
// computed (528 of 1024); each off-diagonal tile also writes its transposed
// mirror and supplies the mirror's tile-maxes as column maxes (smem-staged,
// no atomics, deterministic). FFMA2-packed mainloop identical to R12.
__global__ __launch_bounds__(256, 2) void k_dist(const float* __restrict__ x, int b)
{
    __shared__ float As[32][128];   // k-major; reused as col-max stage later
    __shared__ float Bs[32][128];

    // decode triangular tile index -> (bi, bj), bi <= bj
    int t = blockIdx.x, bi = 0;
    while (t >= NTILE - bi){ t -= NTILE - bi; bi++; }
    const int bj = bi + t;
    const int n0 = bi*128;
    const int m0 = bj*128;

    const float* xb = x + (size_t)b*Nc*Cc;
    const int tid = threadIdx.x;
    const int tx  = tid & 15;
    const int ty  = tid >> 4;
    const int lrow = tid & 127;
    const int lk0  = (tid >> 7) * 4;

    unsigned long long accp[4][8];   // (acc[2ii][j], acc[2ii+1][j])
    #pragma unroll
    for (int ii=0;ii<4;ii++)
        #pragma unroll
        for (int j=0;j<8;j++) accp[ii][j] = 0ull;

    #pragma unroll
    for (int kk=0; kk<2; kk++){
        #pragma unroll
        for (int i=0;i<4;i++){
            int k4 = lk0 + i*8;
            float4 a = *reinterpret_cast<const float4*>(&xb[(size_t)(n0+lrow)*Cc + kk*32 + k4]);
            As[k4+0][lrow]=a.x; As[k4+1][lrow]=a.y; As[k4+2][lrow]=a.z; As[k4+3][lrow]=a.w;
            float4 bb = *reinterpret_cast<const float4*>(&xb[(size_t)(m0+lrow)*Cc + kk*32 + k4]);
            Bs[k4+0][lrow]=bb.x; Bs[k4+1][lrow]=bb.y; Bs[k4+2][lrow]=bb.z; Bs[k4+3][lrow]=bb.w;
        }
        __syncthreads();
        #pragma unroll
        for (int k=0;k<32;k++){
            ulonglong2 ap01 = *reinterpret_cast<const ulonglong2*>(&As[k][ty*4]);
            ulonglong2 ap23 = *reinterpret_cast<const ulonglong2*>(&As[k][64+ty*4]);
            unsigned long long ap[4] = {ap01.x, ap01.y, ap23.x, ap23.y};
            float4 b0 = *reinterpret_cast<const float4*>(&Bs[k][tx*4]);
            float4 b1 = *reinterpret_cast<const float4*>(&Bs[k][64+tx*4]);
            float bv[8]={b0.x,b0.y,b0.z,b0.w,b1.x,b1.y,b1.z,b1.w};
            unsigned long long bb[8];
            #pragma unroll
            for (int j=0;j<8;j++) bb[j] = f32x2_dup(bv[j]);
            #pragma unroll
            for (int ii=0;ii<4;ii++)
                #pragma unroll
                for (int j=0;j<8;j++)
                    f32x2_fma(accp[ii][j], ap[ii], bb[j]);
        }
        __syncthreads();
    }

    // -------- epilogue --------
    float mxx[8];
    #pragma unroll
    for (int cq=0;cq<2;cq++)
        #pragma unroll
        for (int c=0;c<4;c++)
            mxx[cq*4+c] = g_xx[b*Nc + m0 + cq*64 + tx*4 + c];

    // this thread's 8 row indices: ai<4 -> n0+ty*4+ai ; ai>=4 -> n0+64+ty*4+ai-4
    float xn[8];
    #pragma unroll
    for (int ai=0;ai<8;ai++){
        int lr = (ai<4) ? (ty*4+ai) : (64 + ty*4 + (ai-4));
        xn[ai] = g_xx[b*Nc + n0 + lr];
    }

    // unpack accp -> dloc (accp dies here; epilogue-local pressure)
    float dloc[8][8];
    #pragma unroll
    for (int ii=0;ii<4;ii++)
        #pragma unroll
        for (int j=0;j<8;j++){
            float lo, hi;
            f32x2_unpack(accp[ii][j], lo, hi);
            dloc[2*ii+0][j] = 2.f*lo - xn[2*ii+0] - mxx[j];
            dloc[2*ii+1][j] = 2.f*hi - xn[2*ii+1] - mxx[j];
        }

    // direct tile writes + row tile-maxes
    #pragma unroll
    for (int ai=0;ai<8;ai++){
        int lr  = (ai<4) ? (ty*4+ai) : (64 + ty*4 + (ai-4));
        int row = n0 + lr;
        *reinterpret_cast<float4*>(&g_dist[(size_t)row*Nc + m0 + tx*4]) =
            make_float4(dloc[ai][0], dloc[ai][1], dloc[ai][2], dloc[ai][3]);
        *reinterpret_cast<float4*>(&g_dist[(size_t)row*Nc + m0 + 64 + tx*4]) =
            make_float4(dloc[ai][4], dloc[ai][5], dloc[ai][6], dloc[ai][7]);

        float m = dloc[ai][0];
        #pragma unroll
        for (int j=1;j<8;j++) m = fmaxf(m, dloc[ai][j]);
        m = fmaxf(m, __shfl_xor_sync(0xffffffffu, m, 1));
        m = fmaxf(m, __shfl_xor_sync(0xffffffffu, m, 2));
        m = fmaxf(m, __shfl_xor_sync(0xffffffffu, m, 4));
        m = fmaxf(m, __shfl_xor_sync(0xffffffffu, m, 8));
        if (tx == 0) g_tmax[(size_t)row*NTILE + bj] = m;
    }

    if (bi != bj){
        // mirror writes: D[m0+col][n0..] = transposed tile (ai is the
        // contiguous axis -> float4 along ai)
        #pragma unroll
        for (int j=0;j<8;j++){
            int col = m0 + ((j<4) ? (tx*4+j) : (64 + tx*4 + (j-4)));
            *reinterpret_cast<float4*>(&g_dist[(size_t)col*Nc + n0 + ty*4]) =
                make_float4(dloc[0][j], dloc[1][j], dloc[2][j], dloc[3][j]);
            *reinterpret_cast<float4*>(&g_dist[(size_t)col*Nc + n0 + 64 + ty*4]) =
                make_float4(dloc[4][j], dloc[5][j], dloc[6][j], dloc[7][j]);
        }

        // column tile-maxes (= mirror rows' maxes): stage per-thread partials
        // in smem (reuse As: need 16*128 floats <= 32KB), reduce across ty.
        float* Cs = &As[0][0];
        #pragma unroll
        for (int j=0;j<8;j++){
            float m = dloc[0][j];
            #pragma unroll
            for (int ai=1;ai<8;ai++) m = fmaxf(m, dloc[ai][j]);
            int lc = (j<4) ? (tx*4+j) : (64 + tx*4 + (j-4));
            Cs[ty*128 + lc] = m;
        }
        __syncthreads();
        if (tid < 128){
            float m = Cs[tid];
            #pragma unroll
            for (int t2=1;t2<16;t2++) m = fmaxf(m, Cs[t2*128 + tid]);
            g_tmax[(size_t)(m0 + tid)*NTILE + bi] = m;
        }
    }
}

// ---------------- tile-pruned exact top-k(8) + gather + channel max ---------
__device__ __forceinline__ bool knn_better(float v1,int i1,float v2,int i2){
    return (v1 > v2) || (v1 == v2 && i1 < i2);   // matches lax.top_k tie-break
}

__device__ __forceinline__ void knn_insert(float (&v)[8], int (&id)[8], float cv, int ci){
    if (!knn_better(cv,ci,v[7],id[7])) return;
    #pragma unroll
    for (int j=0;j<8;j++){
        if (knn_better(cv,ci,v[j],id[j])){
            float tv=v[j]; int ti=id[j];
            v[j]=cv; id[j]=ci;
            cv=tv; ci=ti;
        }
    }
}

__global__ __launch_bounds__(256) void k_topk(const float* __restrict__ x, int b)
{
    int gw   = (blockIdx.x*256 + threadIdx.x) >> 5;   // warp per n-row
    int lane = threadIdx.x & 31;
    if (gw >= Nc) return;
    const int n = gw;
    const float NEG_INF = __int_as_float(0xff800000);

    // t8 = 8th-largest of the 32 tile maxes. The top-8 tile maxes are 8
    // distinct row elements >= t8, so t8 <= true 8th-best of the row; any
    // tile with max < t8 contains no global-top-8 element.
    float tm  = g_tmax[(size_t)n*NTILE + lane];
    float cur = tm, t8 = tm;
    #pragma unroll
    for (int r=0;r<KNN;r++){
        float m = cur;
        #pragma unroll
        for (int o=16;o;o>>=1) m = fmaxf(m, __shfl_xor_sync(0xffffffffu, m, o));
        t8 = m;
        unsigned msk = __ballot_sync(0xffffffffu, cur == m);
        if (lane == (__ffs(msk) - 1)) cur = NEG_INF;   // drop one instance
    }

    float v[8]; int id[8];
    #pragma unroll
    for (int j=0;j<8;j++){ v[j] = NEG_INF; id[j] = 0x7fffffff; }

    const float* drow = &g_dist[(size_t)n*Nc];
    unsigned keep = __ballot_sync(0xffffffffu, tm >= t8);   // ~8 tiles survive
    while (keep){
        int tile = __ffs(keep) - 1;
        keep &= keep - 1;
        int ci = tile*128 + lane*4;
        float4 d = *reinterpret_cast<const float4*>(&drow[ci]);
        if (d.x >= t8) knn_insert(v,id,d.x,ci+0);
        if (d.y >= t8) knn_insert(v,id,d.y,ci+1);
        if (d.z >= t8) knn_insert(v,id,d.z,ci+2);
        if (d.w >= t8) knn_insert(v,id,d.w,ci+3);
    }

    int knn_idx[8];
    #pragma unroll
    for (int r=0;r<KNN;r++){
        float bv = v[0]; int bi = id[0];
        #pragma unroll
        for (int o=16;o;o>>=1){
            float ov = __shfl_xor_sync(0xffffffffu, bv, o);
            int   oi = __shfl_xor_sync(0xffffffffu, bi, o);
            if (knn_better(ov,oi,bv,bi)){ bv=ov; bi=oi; }
        }
        knn_idx[r] = bi;                 // all lanes agree
        if (id[0] == bi){                // owning lane pops its head
            #pragma unroll
            for (int j=0;j<7;j++){ v[j]=v[j+1]; id[j]=id[j+1]; }
            v[7] = NEG_INF; id[7] = 0x7fffffff;
        }
    }

    // gather neighbor features and take channel-wise max (exact, order-free)
    const float* xb = x + (size_t)b*Nc*Cc;
    #pragma unroll
    for (int cc=0; cc<2; cc++){
        int c = lane + cc*32;
        float m = xb[(size_t)knn_idx[0]*Cc + c];
        #pragma unroll
        for (int r=1;r<KNN;r++)
            m = fmaxf(m, xb[(size_t)knn_idx[r]*Cc + c]);
        g_feat[((size_t)b*Nc + n)*Cc + c] = m;
    }
}

// ---------------- 1x1 conv GEMM + deterministic BN partials -----------------
__global__ __launch_bounds__(128) void k_conv(const float* __restrict__ W,
                                              float* __restrict__ y)
{
    __shared__ float Ws[COc][Cc+1];   // +1 pad: conflict-free per-thread rows
    __shared__ float Fs[CONV_ROWS][Cc];
    const int t    = threadIdx.x;     // 128 threads == one output channel each
    const int blk  = blockIdx.x;
    const int row0 = blk*CONV_ROWS;

    for (int i=t; i<COc*Cc; i+=128) Ws[i>>6][i&63] = W[i];
    for (int i=t; i<CONV_ROWS*Cc; i+=128) Fs[i>>6][i&63] = g_feat[(size_t)row0*Cc + i];
    __syncthreads();

    const int o = t;
    float acc[CONV_ROWS];
    #pragma unroll
    for (int r=0;r<CONV_ROWS;r++) acc[r]=0.f;

    #pragma unroll 8
    for (int k=0;k<Cc;k++){
        float w = Ws[o][k];
        #pragma unroll
        for (int r=0;r<CONV_ROWS;r++)
            acc[r] = fmaf(Fs[r][k], w, acc[r]);
    }

    float s=0.f, s2=0.f;
    #pragma unroll
    for (int r=0;r<CONV_ROWS;r++){
        float yv = acc[r];
        y[(size_t)(row0+r)*COc + o] = yv;
        s  += yv;
        s2 += yv*yv;
    }
    g_psum  [blk*COc + o] = s;
    g_psumsq[blk*COc + o] = s2;
}

// ---------------- BN stats (fixed-order, deterministic) ---------------------
__global__ __launch_bounds__(COc) void k_stats()
{
    int o = threadIdx.x;
    float s=0.f, s2=0.f;
    for (int i=0;i<CONV_BLOCKS;i++){
        s  += g_psum  [i*COc + o];
        s2 += g_psumsq[i*COc + o];
    }
    const float invM = 1.f / (float)ROWS_TOTAL;
    float mean = s * invM;
    float var  = s2 * invM - mean*mean;
    g_mean[o] = mean;
    g_rstd[o] = rsqrtf(var + 1e-5f);
}

// ---------------- BN apply + LeakyReLU --------------------------------------
__device__ __forceinline__ float bn_lrelu(float val, int o,
                                          const float* __restrict__ gamma,
                                          const float* __restrict__ beta){
    float z = (val - g_mean[o]) * g_rstd[o] * gamma[o] + beta[o];
    return z >= 0.f ? z : 0.01f*z;
}

__global__ __launch_bounds__(256) void k_apply(const float* __restrict__ gamma,
                                               const float* __restrict__ beta,
                                               float* __restrict__ y)
{
    int i = blockIdx.x*256 + threadIdx.x;
    const int total4 = Bc*Nc*COc/4;
    if (i >= total4) return;
    int o = (i*4) & (COc-1);
    float4 t = reinterpret_cast<float4*>(y)[i];
    t.x = bn_lrelu(t.x, o+0, gamma, beta);
    t.y = bn_lrelu(t.y, o+1, gamma, beta);
    t.z = bn_lrelu(t.z, o+2, gamma, beta);
    t.w = bn_lrelu(t.w, o+3, gamma, beta);
    reinterpret_cast<float4*>(y)[i] = t;
}

// ---------------- launch ----------------------------------------------------
extern "C" void kernel_launch(void* const* d_in, const int* in_sizes, int n_in,
                              void* d_out, int out_size)
{
    const float* x     = (const float*)d_in[0];
    const float* W     = (const float*)d_in[1];
    const float* gamma = (const float*)d_in[2];
    const float* beta  = (const float*)d_in[3];
    float* y = (float*)d_out;

    k_xx<<<ROWS_TOTAL/8, 256>>>(x);

    for (int b=0; b<Bc; b++){
        k_dist<<<NTRI, 256>>>(x, b);      // symmetric FFMA2 GEMM (528 tiles)
        k_topk<<<Nc/8, 256>>>(x, b);      // tile-pruned exact top-8
    }

    k_conv<<<CONV_BLOCKS, 128>>>(W, y);
    k_stats<<<1, COc>>>();
    k_apply<<<(Bc*Nc*COc/4 + 255)/256, 256>>>(gamma, beta, y);
}